// round 4
// baseline (speedup 1.0000x reference)
#include <cuda_runtime.h>

#define BB 32
#define NN 1024
#define FF 7
#define HID 256
#define MLPH 64
#define OUTD 8
#define THR2 0.09f
#define KCH 128         // K-chunks for MLP layer0
#define K4  14          // float4s per chunk (56 floats); 128*56 = 7168

// ---- device scratch ----
__device__ unsigned g_adj[BB * NN * 32];      // adjacency bitmask, 4MB
__device__ float    g_dinv[BB * NN];          // 1/sqrt(degree)
__device__ float    g_maxp[BB * 16];          // per-pair-block max dist^2 partials
__device__ float    g_upart[BB * 8 * HID];    // per-chunk partials of sum_j s_j h_j
__device__ float    g_speedp[BB * 8];         // per-chunk speed sums
__device__ float    g_mpart[KCH * BB * MLPH]; // MLP layer0 K-chunk partials

// ============================================================================
// kA: blocks [0,512): pairwise adjacency. blocks [512,640): MLP0 chunk GEMM.
// ============================================================================
__global__ __launch_bounds__(256, 5) void kA(const float* __restrict__ x,
                                             const float* __restrict__ Wm0) {
    __shared__ float sbuf[K4 * MLPH * 4 + K4 * BB * 4 + 16];   // ~21.5KB
    int t = threadIdx.x;

    if (blockIdx.x < 512) {
        float2* s_pts = (float2*)sbuf;            // [NN] 8KB
        float*  s_max = sbuf + 2 * NN;            // [8]
        int b = blockIdx.x >> 4;
        int blk16 = blockIdx.x & 15;
        int rowbase = blk16 << 6;
        int lane = t & 31, w = t >> 5;

        for (int j = t; j < NN; j += 256) {
            const float* xr = x + ((size_t)b * NN + j) * FF;
            s_pts[j] = make_float2(xr[1], xr[2]);
        }
        __syncthreads();

        int i0 = rowbase + w * 8;
        float xi[8], yi[8]; unsigned word[8];
#pragma unroll
        for (int r = 0; r < 8; ++r) {
            float2 p = s_pts[i0 + r]; xi[r] = p.x; yi[r] = p.y; word[r] = 0u;
        }
        float mx = 0.f;
        for (int jw = 0; jw < 32; ++jw) {
            float2 pj = s_pts[jw * 32 + lane];
#pragma unroll
            for (int r = 0; r < 8; ++r) {
                float dx = xi[r] - pj.x, dy = yi[r] - pj.y;
                float d2 = fmaf(dx, dx, dy * dy);
                mx = fmaxf(mx, d2);
                unsigned m = __ballot_sync(0xffffffffu, d2 < THR2);
                if (lane == jw) word[r] = m;
            }
        }
#pragma unroll
        for (int r = 0; r < 8; ++r) {
            int i = i0 + r;
            g_adj[((size_t)b * NN + i) * 32 + lane] = word[r];
            int deg = __reduce_add_sync(0xffffffffu, __popc(word[r]));
            if (lane == 0) g_dinv[b * NN + i] = rsqrtf((float)deg);
        }
        for (int o = 16; o > 0; o >>= 1)
            mx = fmaxf(mx, __shfl_xor_sync(0xffffffffu, mx, o));
        if (lane == 0) s_max[w] = mx;
        __syncthreads();
        if (t == 0) {
            float m = s_max[0];
#pragma unroll
            for (int k = 1; k < 8; ++k) m = fmaxf(m, s_max[k]);
            g_maxp[b * 16 + blk16] = m;
        }
    } else {
        int c = blockIdx.x - 512;
        float4* sw4 = (float4*)sbuf;                       // [K4][64]
        float4* sx4 = (float4*)(sbuf + K4 * MLPH * 4);     // [K4][32]
        const float4* W4 = (const float4*)Wm0;
        const float4* X4 = (const float4*)x;

        for (int i = t; i < MLPH * K4; i += 256) {         // 896
            int h = i / K4, k = i % K4;
            sw4[k * MLPH + h] = W4[(size_t)h * 1792 + c * K4 + k];
        }
        for (int i = t; i < BB * K4; i += 256) {           // 448
            int b = i / K4, k = i % K4;
            sx4[k * BB + b] = X4[(size_t)b * 1792 + c * K4 + k];
        }
        __syncthreads();

        if (t < 128) {
            int hb = t & 15;       // heads hb + 16j
            int bb = t >> 4;       // batches bb + 8i
            float acc[4][4] = {};
#pragma unroll
            for (int k = 0; k < K4; ++k) {
                float4 xv[4];
#pragma unroll
                for (int i = 0; i < 4; ++i) xv[i] = sx4[k * BB + bb + 8 * i];
#pragma unroll
                for (int j = 0; j < 4; ++j) {
                    float4 wv = sw4[k * MLPH + hb + 16 * j];
#pragma unroll
                    for (int i = 0; i < 4; ++i) {
                        acc[i][j] = fmaf(xv[i].x, wv.x, acc[i][j]);
                        acc[i][j] = fmaf(xv[i].y, wv.y, acc[i][j]);
                        acc[i][j] = fmaf(xv[i].z, wv.z, acc[i][j]);
                        acc[i][j] = fmaf(xv[i].w, wv.w, acc[i][j]);
                    }
                }
            }
#pragma unroll
            for (int i = 0; i < 4; ++i)
#pragma unroll
                for (int j = 0; j < 4; ++j)
                    g_mpart[((size_t)c * BB + bb + 8 * i) * MLPH + hb + 16 * j] = acc[i][j];
        }
    }
}

// ============================================================================
// kB: sparse graph pass. Block = (batch, 128-row chunk). 256 blocks.
// Coalesced adj-word staging into smem, thread-per-row bit scan.
// ============================================================================
__global__ __launch_bounds__(256) void kB(const float* __restrict__ x,
                                          const float* __restrict__ W1,
                                          const float* __restrict__ b1) {
    __shared__ unsigned s_words[128 * 32];   // 16KB
    __shared__ float2   s_pts[NN];           // 8KB
    __shared__ float    s_dinv[NN];          // 4KB
    __shared__ float4   s_P[128];            // 2KB (Px,Py,S,-)
    __shared__ float    sred[128];
    int b = blockIdx.x >> 3, seg = blockIdx.x & 7;
    int t = threadIdx.x;
    int row0 = seg * 128;

    for (int j = t; j < NN; j += 256) {
        const float* xr = x + ((size_t)b * NN + j) * FF;
        s_pts[j]  = make_float2(xr[1], xr[2]);
        s_dinv[j] = g_dinv[b * NN + j];
    }
    const unsigned* adjb = g_adj + ((size_t)b * NN + row0) * 32;
    for (int i = t; i < 128 * 32; i += 256) s_words[i] = adjb[i];
    __syncthreads();

    if (t < 128) {
        int row = row0 + t;
        float wsum = 0.f, px = 0.f, py = 0.f;
        const unsigned* wr = s_words + t * 32;
#pragma unroll 8
        for (int wd = 0; wd < 32; ++wd) {
            unsigned m = wr[wd];
            int base = wd * 32;
            while (m) {
                int j = base + __ffs(m) - 1;
                m &= m - 1;
                float dj = s_dinv[j];
                float2 p = s_pts[j];
                wsum += dj;
                px = fmaf(dj, p.x, px);
                py = fmaf(dj, p.y, py);
            }
        }
        float di = s_dinv[row];
        s_P[t] = make_float4(di * px, di * py, di * wsum, 0.f);
        const float* xr = x + ((size_t)b * NN + row) * FF;
        sred[t] = sqrtf(fmaf(xr[3], xr[3], xr[4] * xr[4]));
    }
    __syncthreads();
    for (int o = 64; o > 0; o >>= 1) {
        if (t < o) sred[t] += sred[t + o];
        __syncthreads();
    }
    if (t == 0) g_speedp[b * 8 + seg] = sred[0];

    float w10 = W1[2 * t], w11 = W1[2 * t + 1], bk = b1[t];
    float acc = 0.f;
#pragma unroll 8
    for (int r = 0; r < 128; ++r) {
        float4 P = s_P[r];
        float h = fmaxf(fmaf(w10, P.x, fmaf(w11, P.y, bk)), 0.f);
        acc = fmaf(P.z, h, acc);
    }
    g_upart[(b * 8 + seg) * HID + t] = acc;
}

// ============================================================================
// k3: per-batch finals.
// ============================================================================
__global__ void k3_final(const float* __restrict__ W2,  const float* __restrict__ b2,
                         const float* __restrict__ Wfc, const float* __restrict__ bfc,
                         const float* __restrict__ Wg,  const float* __restrict__ bg,
                         const float* __restrict__ Wm1, const float* __restrict__ bm1,
                         const float* __restrict__ bm0,
                         const float* __restrict__ Wp,  const float* __restrict__ bp,
                         float* __restrict__ out) {
    __shared__ float sm[HID], smid[HID], sgcn[HID], sglo[OUTD];
    __shared__ float sy0[MLPH], sy1[MLPH];
    int b = blockIdx.x, t = threadIdx.x;

    float u = 0.f;
#pragma unroll
    for (int c = 0; c < 8; ++c) u += g_upart[(b * 8 + c) * HID + t];
    sm[t] = u * (1.0f / 1024.0f);

    if (t < MLPH) {
        float a = 0.f;
#pragma unroll 8
        for (int c = 0; c < KCH; ++c)
            a += g_mpart[((size_t)c * BB + b) * MLPH + t];
        sy0[t] = fmaxf(a + bm0[t], 0.f);
    }
    __syncthreads();

    if (t < MLPH) {
        float a = bm1[t];
        const float* w = Wm1 + t * MLPH;
#pragma unroll 8
        for (int j = 0; j < MLPH; ++j) a = fmaf(w[j], sy0[j], a);
        sy1[t] = fmaxf(a, 0.f);
    }

    float a = b2[t];
    const float4* w2r = (const float4*)(W2 + (size_t)t * HID);
    const float4* smv = (const float4*)sm;
#pragma unroll 8
    for (int j = 0; j < HID / 4; ++j) {
        float4 wv = w2r[j], mv = smv[j];
        a = fmaf(wv.x, mv.x, a); a = fmaf(wv.y, mv.y, a);
        a = fmaf(wv.z, mv.z, a); a = fmaf(wv.w, mv.w, a);
    }
    smid[t] = a;
    __syncthreads();

    a = bfc[t];
    const float4* wfr  = (const float4*)(Wfc + (size_t)t * HID);
    const float4* smdv = (const float4*)smid;
#pragma unroll 8
    for (int j = 0; j < HID / 4; ++j) {
        float4 wv = wfr[j], mv = smdv[j];
        a = fmaf(wv.x, mv.x, a); a = fmaf(wv.y, mv.y, a);
        a = fmaf(wv.z, mv.z, a); a = fmaf(wv.w, mv.w, a);
    }
    sgcn[t] = a;

    if (t < OUTD) {
        float avg = 0.f;
#pragma unroll
        for (int c = 0; c < 8; ++c) avg += g_speedp[b * 8 + c];
        avg *= (1.0f / 1024.0f);
        float mx = g_maxp[b * 16];
#pragma unroll
        for (int k = 1; k < 16; ++k) mx = fmaxf(mx, g_maxp[b * 16 + k]);
        float den = rsqrtf(mx);
        sglo[t] = fmaxf(fmaf(Wg[t * 2], avg, fmaf(Wg[t * 2 + 1], den, bg[t])), 0.f);
    }
    __syncthreads();

    if (t < OUTD) {
        float o = bp[t];
        const float* wp = Wp + t * (MLPH + HID + OUTD);
#pragma unroll 8
        for (int j = 0; j < MLPH; ++j) o = fmaf(wp[j], sy1[j], o);
#pragma unroll 8
        for (int j = 0; j < HID;  ++j) o = fmaf(wp[MLPH + j], sgcn[j], o);
#pragma unroll
        for (int j = 0; j < OUTD; ++j) o = fmaf(wp[MLPH + HID + j], sglo[j], o);
        out[b * OUTD + t] = o;
    }
}

extern "C" void kernel_launch(void* const* d_in, const int* in_sizes, int n_in,
                              void* d_out, int out_size) {
    const float* x   = (const float*)d_in[0];
    const float* W1  = (const float*)d_in[1];
    const float* b1  = (const float*)d_in[2];
    const float* W2  = (const float*)d_in[3];
    const float* b2  = (const float*)d_in[4];
    const float* Wfc = (const float*)d_in[5];
    const float* bfc = (const float*)d_in[6];
    const float* Wg  = (const float*)d_in[7];
    const float* bg  = (const float*)d_in[8];
    const float* Wm0 = (const float*)d_in[9];
    const float* bm0 = (const float*)d_in[10];
    const float* Wm1 = (const float*)d_in[11];
    const float* bm1 = (const float*)d_in[12];
    const float* Wp  = (const float*)d_in[13];
    const float* bp  = (const float*)d_in[14];
    float* out = (float*)d_out;

    kA<<<640, 256>>>(x, Wm0);
    kB<<<256, 256>>>(x, W1, b1);
    k3_final<<<32, 256>>>(W2, b2, Wfc, bfc, Wg, bg, Wm1, bm1, bm0, Wp, bp, out);
}